// round 10
// baseline (speedup 1.0000x reference)
#include <cuda_runtime.h>
#include <math.h>

#define Bn   32
#define NKV  4096
#define DIN  256
#define NQ   16
#define Sd   256          // slot dim (S) — confirmed 256, not 512!
#define Hn   8
#define HD   32           // S / H
#define HM   512
#define HQ   128          // Hn*NQ
#define EPSn 1e-8f
#define KPB  32
#define QPITCH 261        // odd pitch -> conflict-free strided smem reads
#define UKC  64
#define KSCALE 0.17677669529663687f   // hd^-0.5 = 1/sqrt(32)

// ---------------- scratch (static device globals; no allocations) ----------------
__device__ float g_x[Bn*NKV*DIN];
__device__ float g_k[Bn*NKV*Sd];
__device__ float g_v[Bn*NKV*Sd];
__device__ float g_attn[(size_t)Bn*NKV*HQ];
__device__ float g_q[Bn*NQ*Sd];
__device__ float g_s[Bn*NQ*Sd];
__device__ float g_slots[Bn*NQ*Sd];
__device__ float g_tmp[Bn*NQ*Sd];
__device__ float g_m[Bn*NQ*Sd];
__device__ float g_upd[Bn*NQ*Sd];
__device__ float g_h1[Bn*NQ*HM];
__device__ float g_gi[Bn*NQ*3*Sd];
__device__ float g_gh[Bn*NQ*3*Sd];
__device__ float g_denom[Bn*HQ];

// ---------------- LayerNorm: one block per row ----------------
template<int COLS>
__global__ void __launch_bounds__(256) ln_kernel(const float* __restrict__ in,
    const float* __restrict__ gamma, const float* __restrict__ beta,
    float* __restrict__ out)
{
  __shared__ float sa[8], sb[8];
  const int row = blockIdx.x;
  const float* x = in + (size_t)row * COLS;
  float* y = out + (size_t)row * COLS;
  const int tid = threadIdx.x;
  float s = 0.f, s2 = 0.f;
  for (int c = tid; c < COLS; c += 256) { float v = x[c]; s += v; s2 += v*v; }
  const int lane = tid & 31, w = tid >> 5;
  #pragma unroll
  for (int o = 16; o; o >>= 1) {
    s  += __shfl_xor_sync(0xffffffffu, s,  o);
    s2 += __shfl_xor_sync(0xffffffffu, s2, o);
  }
  if (!lane) { sa[w] = s; sb[w] = s2; }
  __syncthreads();
  float ts = 0.f, ts2 = 0.f;
  #pragma unroll
  for (int i = 0; i < 8; i++) { ts += sa[i]; ts2 += sb[i]; }
  const float mean = ts * (1.0f / COLS);
  const float var  = ts2 * (1.0f / COLS) - mean * mean;
  const float rstd = rsqrtf(var + 1e-5f);
  for (int c = tid; c < COLS; c += 256)
    y[c] = (x[c] - mean) * rstd * gamma[c] + beta[c];
}

// ---------------- GEMM: C[M,N] = alpha * A[M,K] @ B[N,K]^T (+bias)(+residual)(relu) ----------------
template<int BM, int BN, int BK, int TM, int TN>
__global__ void __launch_bounds__(256) gemm_nt(
    const float* __restrict__ A, const float* __restrict__ Bm, float* __restrict__ C,
    int M, int N, int K, float alpha, const float* __restrict__ bias,
    const float* __restrict__ residual, int relu)
{
  __shared__ float As[BK][BM];
  __shared__ float Bs[BK][BN];
  const int tid = threadIdx.x;
  const int bn = blockIdx.x * BN, bm = blockIdx.y * BM;
  const int TXN = BN / TN;
  const int tx = tid % TXN, ty = tid / TXN;
  float acc[TM][TN];
  #pragma unroll
  for (int i = 0; i < TM; i++)
    #pragma unroll
    for (int j = 0; j < TN; j++) acc[i][j] = 0.f;

  for (int k0 = 0; k0 < K; k0 += BK) {
    for (int i = tid * 4; i < BM * BK; i += 1024) {
      int r = i / BK, c = i % BK;
      float4 a4 = *(const float4*)(A + (size_t)(bm + r) * K + k0 + c);
      As[c][r] = a4.x; As[c+1][r] = a4.y; As[c+2][r] = a4.z; As[c+3][r] = a4.w;
    }
    for (int i = tid * 4; i < BN * BK; i += 1024) {
      int r = i / BK, c = i % BK;
      float4 b4 = *(const float4*)(Bm + (size_t)(bn + r) * K + k0 + c);
      Bs[c][r] = b4.x; Bs[c+1][r] = b4.y; Bs[c+2][r] = b4.z; Bs[c+3][r] = b4.w;
    }
    __syncthreads();
    #pragma unroll
    for (int kk = 0; kk < BK; kk++) {
      float a[TM], bfr[TN];
      #pragma unroll
      for (int i = 0; i < TM; i++) a[i] = As[kk][ty * TM + i];
      #pragma unroll
      for (int j = 0; j < TN; j++) bfr[j] = Bs[kk][tx * TN + j];
      #pragma unroll
      for (int i = 0; i < TM; i++)
        #pragma unroll
        for (int j = 0; j < TN; j++) acc[i][j] += a[i] * bfr[j];
    }
    __syncthreads();
  }
  #pragma unroll
  for (int i = 0; i < TM; i++) {
    const int m = bm + ty * TM + i;
    #pragma unroll
    for (int j = 0; j < TN; j++) {
      const int n = bn + tx * TN + j;
      float v = acc[i][j] * alpha;
      if (bias)     v += bias[n];
      if (residual) v += residual[(size_t)m * N + n];
      if (relu)     v = fmaxf(v, 0.f);
      C[(size_t)m * N + n] = v;
    }
  }
}

// ---------------- attention: logits + joint softmax over (h,q)=128, per key ----------------
// grid (B, NKV/KPB), 128 threads; thread j = h*NQ + q
__global__ void __launch_bounds__(128) attn_fast(
    const float* __restrict__ Kmat,   // [B*NKV, S], pre-scaled by hd^-0.5
    const float* __restrict__ Qmat,   // [B*NQ, S]
    float* __restrict__ attn)         // [B*NKV, HQ]
{
  __shared__ float Qs[NQ * QPITCH];
  __shared__ float Ks[Sd];
  __shared__ float red[4], red2[4];
  const int b = blockIdx.x;
  const int chunk = blockIdx.y;
  const int j = threadIdx.x;
  const int h = j >> 4;
  const int q = j & 15;
  const int lane = j & 31, w = j >> 5;
  const float* qb = Qmat + (size_t)b * NQ * Sd;
  for (int qq = 0; qq < NQ; qq++)
    for (int c = j; c < Sd; c += 128)
      Qs[qq * QPITCH + c] = qb[qq * Sd + c];
  __syncthreads();

  const float* qrow = Qs + q * QPITCH + h * HD;
  for (int kk = 0; kk < KPB; kk++) {
    const int key = chunk * KPB + kk;
    const float* krow = Kmat + ((size_t)b * NKV + key) * Sd;
    Ks[j * 2]     = krow[j * 2];
    Ks[j * 2 + 1] = krow[j * 2 + 1];
    __syncthreads();
    float s = 0.f;
    #pragma unroll
    for (int d = 0; d < HD; d++) s += Ks[h * HD + d] * qrow[d];
    // block max over 128
    float m = s;
    #pragma unroll
    for (int o = 16; o; o >>= 1) m = fmaxf(m, __shfl_xor_sync(0xffffffffu, m, o));
    if (!lane) red[w] = m;
    __syncthreads();
    m = fmaxf(fmaxf(red[0], red[1]), fmaxf(red[2], red[3]));
    const float e = __expf(s - m);
    float t = e;
    #pragma unroll
    for (int o = 16; o; o >>= 1) t += __shfl_xor_sync(0xffffffffu, t, o);
    if (!lane) red2[w] = t;
    __syncthreads();
    t = red2[0] + red2[1] + red2[2] + red2[3];
    attn[((size_t)b * NKV + key) * HQ + j] = e / t;
    __syncthreads();
  }
}

__global__ void denom_reduce(const float* __restrict__ attn, float* __restrict__ denom)
{
  const int b = blockIdx.x, j = threadIdx.x;
  float s = 0.f;
  for (int k = 0; k < NKV; k++) s += attn[((size_t)b * NKV + k) * HQ + j];
  denom[b * HQ + j] = s;
}

// vis[b,k,q] = sum_h attn[b,k,h*NQ+q]
__global__ void vis_kernel(const float* __restrict__ attn, float* __restrict__ vis)
{
  const int idx = blockIdx.x * blockDim.x + threadIdx.x;
  if (idx >= Bn * NKV * NQ) return;
  const int q = idx & 15;
  const int bk = idx >> 4;
  float s = 0.f;
  #pragma unroll
  for (int h = 0; h < Hn; h++) s += attn[(size_t)bk * HQ + h * NQ + q];
  vis[idx] = s;
}

// ---------------- updates: tiled over keys; grid (B, H), 256 threads ----------------
// upd[b,q,h*HD+d] = (sum_k attn[b,k,h*16+q]*V[b,k,h*HD+d]) / (denom+eps)
__global__ void __launch_bounds__(256) updates_kernel(
    const float* __restrict__ attn, const float* __restrict__ denom,
    const float* __restrict__ V, float* __restrict__ upd)
{
  __shared__ float As[UKC][NQ];
  __shared__ float Vs[UKC][HD];
  __shared__ float invd[NQ];
  const int b = blockIdx.x, h = blockIdx.y;
  const int tid = threadIdx.x;
  const int q0 = tid >> 5;       // 0..7 (2 q's each)
  const int d  = tid & 31;
  if (tid < NQ) invd[tid] = 1.0f / (denom[b * HQ + h * NQ + tid] + EPSn);
  __syncthreads();
  float acc[2] = {0.f, 0.f};
  for (int k0 = 0; k0 < NKV; k0 += UKC) {
    {
      // attn tile: 64 keys x 16 q = 1024 floats = 256 threads x float4
      int key = tid >> 2, part = (tid & 3) * 4;
      float4 a4 = *(const float4*)(attn + ((size_t)b * NKV + k0 + key) * HQ + h * NQ + part);
      As[key][part+0] = a4.x * invd[part+0];
      As[key][part+1] = a4.y * invd[part+1];
      As[key][part+2] = a4.z * invd[part+2];
      As[key][part+3] = a4.w * invd[part+3];
    }
    #pragma unroll
    for (int r = 0; r < 2; r++) {
      // V tile: 64 keys x 32 d = 2048 floats = 512 float4 over 2 rounds
      int idx = tid + r * 256;
      int key = idx >> 3, part = (idx & 7) * 4;
      float4 v4 = *(const float4*)(V + ((size_t)b * NKV + k0 + key) * Sd + h * HD + part);
      *(float4*)(&Vs[key][part]) = v4;
    }
    __syncthreads();
    #pragma unroll 8
    for (int kk = 0; kk < UKC; kk++) {
      const float vv = Vs[kk][d];
      acc[0] += As[kk][q0 * 2 + 0] * vv;
      acc[1] += As[kk][q0 * 2 + 1] * vv;
    }
    __syncthreads();
  }
  #pragma unroll
  for (int i = 0; i < 2; i++) {
    const int qi = q0 * 2 + i;
    upd[((size_t)b * NQ + qi) * Sd + h * HD + d] = acc[i];
  }
}

// ---------------- GRU pointwise (gates r,z,n) ----------------
__global__ void gru_kernel(const float* __restrict__ gi, const float* __restrict__ gh,
                           const float* __restrict__ hprev, float* __restrict__ out)
{
  const int idx = blockIdx.x * blockDim.x + threadIdx.x;
  if (idx >= Bn * NQ * Sd) return;
  const int row = idx >> 8, col = idx & (Sd - 1);
  const float* gir = gi + (size_t)row * 3 * Sd;
  const float* ghr = gh + (size_t)row * 3 * Sd;
  const float ir = gir[col], iz = gir[Sd + col], in_ = gir[2 * Sd + col];
  const float hr = ghr[col], hz = ghr[Sd + col], hn = ghr[2 * Sd + col];
  const float r = 1.0f / (1.0f + __expf(-(ir + hr)));
  const float z = 1.0f / (1.0f + __expf(-(iz + hz)));
  const float n = tanhf(in_ + r * hn);
  out[idx] = (1.0f - z) * n + z * hprev[idx];
}

__global__ void bcast_slots(const float* __restrict__ s0, float* __restrict__ slots)
{
  const int idx = blockIdx.x * blockDim.x + threadIdx.x;
  if (idx < Bn * NQ * Sd) slots[idx] = s0[idx & (NQ * Sd - 1)];
}

__global__ void copy_kernel(const float* __restrict__ src, float* __restrict__ dst, int n)
{
  const int idx = blockIdx.x * blockDim.x + threadIdx.x;
  if (idx < n) dst[idx] = src[idx];
}

// ---------------- launch ----------------
extern "C" void kernel_launch(void* const* d_in, const int* in_sizes, int n_in,
                              void* d_out, int out_size)
{
  // dict order, fp32, element counts (S=256 — verified against setup_inputs)
  const float* slots0 = (const float*)d_in[0];   // 4096
  const float* inputs = (const float*)d_in[1];   // 33554432
  const float* nin_g  = (const float*)d_in[2];   // 256
  const float* nin_b  = (const float*)d_in[3];
  const float* ns_g   = (const float*)d_in[4];   // 256
  const float* ns_b   = (const float*)d_in[5];
  const float* nm_g   = (const float*)d_in[6];
  const float* nm_b   = (const float*)d_in[7];
  const float* Wq     = (const float*)d_in[8];   // 65536
  const float* Wk     = (const float*)d_in[9];
  const float* Wv     = (const float*)d_in[10];
  const float* wih    = (const float*)d_in[11];  // 196608
  const float* whh    = (const float*)d_in[12];
  const float* bih    = (const float*)d_in[13];  // 768
  const float* bhh    = (const float*)d_in[14];
  const float* w1     = (const float*)d_in[15];  // 131072 (512x256)
  const float* b1     = (const float*)d_in[16];  // 512
  const float* w2     = (const float*)d_in[17];  // 131072 (256x512)
  const float* b2     = (const float*)d_in[18];  // 256
  float* out = (float*)d_out;

  float *px, *pk, *pv, *pattn, *pq, *ps, *pslots, *ptmp, *pm, *pupd, *ph1, *pgi, *pgh, *pdenom;
  cudaGetSymbolAddress((void**)&px, g_x);
  cudaGetSymbolAddress((void**)&pk, g_k);
  cudaGetSymbolAddress((void**)&pv, g_v);
  cudaGetSymbolAddress((void**)&pattn, g_attn);
  cudaGetSymbolAddress((void**)&pq, g_q);
  cudaGetSymbolAddress((void**)&ps, g_s);
  cudaGetSymbolAddress((void**)&pslots, g_slots);
  cudaGetSymbolAddress((void**)&ptmp, g_tmp);
  cudaGetSymbolAddress((void**)&pm, g_m);
  cudaGetSymbolAddress((void**)&pupd, g_upd);
  cudaGetSymbolAddress((void**)&ph1, g_h1);
  cudaGetSymbolAddress((void**)&pgi, g_gi);
  cudaGetSymbolAddress((void**)&pgh, g_gh);
  cudaGetSymbolAddress((void**)&pdenom, g_denom);

  const int MROWS = Bn * NKV;     // 131072
  const int SR    = Bn * NQ;      // 512
  const long long SLOTS_N = (long long)Bn * NQ * Sd;      // 131072
  const long long VIS_N   = (long long)Bn * NKV * NQ;     // 2097152

  float* slots_out = out;
  float* vis_out = ((long long)out_size >= SLOTS_N + VIS_N) ? (out + SLOTS_N) : nullptr;

  bcast_slots<<<(unsigned)((SLOTS_N + 255) / 256), 256>>>(slots0, pslots);
  ln_kernel<DIN><<<MROWS, 256>>>(inputs, nin_g, nin_b, px);
  // K (scaled by hd^-0.5) and V projections: [131072,256] @ [256,256]^T
  gemm_nt<128,128,8,8,8><<<dim3(Sd/128, MROWS/128), 256>>>(px, Wk, pk, MROWS, Sd, DIN, KSCALE, nullptr, nullptr, 0);
  gemm_nt<128,128,8,8,8><<<dim3(Sd/128, MROWS/128), 256>>>(px, Wv, pv, MROWS, Sd, DIN, 1.0f,   nullptr, nullptr, 0);

  for (int it = 0; it < 3; it++) {
    ln_kernel<Sd><<<SR, 256>>>(pslots, ns_g, ns_b, ps);
    gemm_nt<64,64,8,4,4><<<dim3(Sd/64, SR/64), 256>>>(ps, Wq, pq, SR, Sd, Sd, 1.f, nullptr, nullptr, 0);
    attn_fast<<<dim3(Bn, NKV/KPB), 128>>>(pk, pq, pattn);
    denom_reduce<<<Bn, HQ>>>(pattn, pdenom);
    if (it == 2 && vis_out)
      vis_kernel<<<(unsigned)((VIS_N + 255) / 256), 256>>>(pattn, vis_out);
    updates_kernel<<<dim3(Bn, Hn), 256>>>(pattn, pdenom, pv, pupd);
    gemm_nt<64,64,8,4,4><<<dim3(3*Sd/64, SR/64), 256>>>(pupd,   wih, pgi, SR, 3*Sd, Sd, 1.f, bih, nullptr, 0);
    gemm_nt<64,64,8,4,4><<<dim3(3*Sd/64, SR/64), 256>>>(pslots, whh, pgh, SR, 3*Sd, Sd, 1.f, bhh, nullptr, 0);
    gru_kernel<<<(unsigned)((SLOTS_N + 255) / 256), 256>>>(pgi, pgh, pslots, ptmp);
    ln_kernel<Sd><<<SR, 256>>>(ptmp, nm_g, nm_b, pm);
    gemm_nt<64,64,8,4,4><<<dim3(HM/64, SR/64), 256>>>(pm,  w1, ph1,    SR, HM, Sd, 1.f, b1, nullptr, 1);
    gemm_nt<64,64,8,4,4><<<dim3(Sd/64, SR/64), 256>>>(ph1, w2, pslots, SR, Sd, HM, 1.f, b2, ptmp,  0);
  }
  copy_kernel<<<(unsigned)((SLOTS_N + 255) / 256), 256>>>(pslots, slots_out, (int)SLOTS_N);
}

// round 11
// speedup vs baseline: 1.3946x; 1.3946x over previous
#include <cuda_runtime.h>
#include <math.h>

#define Bn   32
#define NKV  4096
#define DIN  256
#define NQ   16
#define Sd   256
#define Hn   8
#define HD   32
#define HM   512
#define HQ   128          // Hn*NQ
#define EPSn 1e-8f
#define UKC  64
#define USPL 8            // updates key-split
#define KT   128          // keys per attention block
#define NCH  (NKV/KT)     // 32
#define KSCALE 0.17677669529663687f   // 1/sqrt(32)

// attn_fused smem layout (floats)
#define QS_OFF  0
#define QS_SZ   (Hn*NQ*33)          // 4224
#define LG_OFF  (QS_OFF + QS_SZ)
#define LG_SZ   (KT*129)            // 16512
#define DWS_OFF (LG_OFF + LG_SZ)
#define DWS_SZ  (8*HQ)              // 1024
#define ATTN_SMEM_BYTES ((DWS_OFF + DWS_SZ) * 4)

// ---------------- scratch (static device globals; no allocations) ----------------
__device__ float g_x[Bn*NKV*DIN];
__device__ float g_k[Bn*NKV*Sd];
__device__ float g_v[Bn*NKV*Sd];
__device__ float g_attn[(size_t)Bn*NKV*HQ];
__device__ float g_q[Bn*NQ*Sd];
__device__ float g_s[Bn*NQ*Sd];
__device__ float g_slots[Bn*NQ*Sd];
__device__ float g_tmp[Bn*NQ*Sd];
__device__ float g_m[Bn*NQ*Sd];
__device__ float g_upd[Bn*NQ*Sd];
__device__ float g_updp[USPL*Bn*NQ*Sd];
__device__ float g_h1[Bn*NQ*HM];
__device__ float g_gi[Bn*NQ*3*Sd];
__device__ float g_gh[Bn*NQ*3*Sd];
__device__ float g_dpart[Bn*NCH*HQ];
__device__ float g_denom[Bn*HQ];

// ---------------- LayerNorm: one block per row ----------------
template<int COLS>
__global__ void __launch_bounds__(256) ln_kernel(const float* __restrict__ in,
    const float* __restrict__ gamma, const float* __restrict__ beta,
    float* __restrict__ out)
{
  __shared__ float sa[8], sb[8];
  const int row = blockIdx.x;
  const float* x = in + (size_t)row * COLS;
  float* y = out + (size_t)row * COLS;
  const int tid = threadIdx.x;
  float s = 0.f, s2 = 0.f;
  for (int c = tid; c < COLS; c += 256) { float v = x[c]; s += v; s2 += v*v; }
  const int lane = tid & 31, w = tid >> 5;
  #pragma unroll
  for (int o = 16; o; o >>= 1) {
    s  += __shfl_xor_sync(0xffffffffu, s,  o);
    s2 += __shfl_xor_sync(0xffffffffu, s2, o);
  }
  if (!lane) { sa[w] = s; sb[w] = s2; }
  __syncthreads();
  float ts = 0.f, ts2 = 0.f;
  #pragma unroll
  for (int i = 0; i < 8; i++) { ts += sa[i]; ts2 += sb[i]; }
  const float mean = ts * (1.0f / COLS);
  const float var  = ts2 * (1.0f / COLS) - mean * mean;
  const float rstd = rsqrtf(var + 1e-5f);
  for (int c = tid; c < COLS; c += 256)
    y[c] = (x[c] - mean) * rstd * gamma[c] + beta[c];
}

// ---------------- GEMM: C[M,N] = alpha * A[M,K] @ B[N,K]^T (+bias)(+residual)(relu) ----------------
template<int BM, int BN, int BK, int TM, int TN>
__global__ void __launch_bounds__(256) gemm_nt(
    const float* __restrict__ A, const float* __restrict__ Bm, float* __restrict__ C,
    int M, int N, int K, float alpha, const float* __restrict__ bias,
    const float* __restrict__ residual, int relu)
{
  __shared__ float As[BK][BM];
  __shared__ float Bs[BK][BN];
  const int tid = threadIdx.x;
  const int bn = blockIdx.x * BN, bm = blockIdx.y * BM;
  const int TXN = BN / TN;
  const int tx = tid % TXN, ty = tid / TXN;
  float acc[TM][TN];
  #pragma unroll
  for (int i = 0; i < TM; i++)
    #pragma unroll
    for (int j = 0; j < TN; j++) acc[i][j] = 0.f;

  for (int k0 = 0; k0 < K; k0 += BK) {
    for (int i = tid * 4; i < BM * BK; i += 1024) {
      int r = i / BK, c = i % BK;
      float4 a4 = *(const float4*)(A + (size_t)(bm + r) * K + k0 + c);
      As[c][r] = a4.x; As[c+1][r] = a4.y; As[c+2][r] = a4.z; As[c+3][r] = a4.w;
    }
    for (int i = tid * 4; i < BN * BK; i += 1024) {
      int r = i / BK, c = i % BK;
      float4 b4 = *(const float4*)(Bm + (size_t)(bn + r) * K + k0 + c);
      Bs[c][r] = b4.x; Bs[c+1][r] = b4.y; Bs[c+2][r] = b4.z; Bs[c+3][r] = b4.w;
    }
    __syncthreads();
    #pragma unroll
    for (int kk = 0; kk < BK; kk++) {
      float a[TM], bfr[TN];
      #pragma unroll
      for (int i = 0; i < TM; i++) a[i] = As[kk][ty * TM + i];
      #pragma unroll
      for (int j = 0; j < TN; j++) bfr[j] = Bs[kk][tx * TN + j];
      #pragma unroll
      for (int i = 0; i < TM; i++)
        #pragma unroll
        for (int j = 0; j < TN; j++) acc[i][j] += a[i] * bfr[j];
    }
    __syncthreads();
  }
  #pragma unroll
  for (int i = 0; i < TM; i++) {
    const int m = bm + ty * TM + i;
    #pragma unroll
    for (int j = 0; j < TN; j++) {
      const int n = bn + tx * TN + j;
      float v = acc[i][j] * alpha;
      if (bias)     v += bias[n];
      if (residual) v += residual[(size_t)m * N + n];
      if (relu)     v = fmaxf(v, 0.f);
      C[(size_t)m * N + n] = v;
    }
  }
}

// ---------------- fused attention: logits + softmax + denom partials + vis ----------------
// grid (B, NCH); 256 threads = 8 warps; KT=128 keys per block.
__global__ void __launch_bounds__(256) attn_fused(
    const float* __restrict__ Kmat,   // [B*NKV, S], pre-scaled
    const float* __restrict__ Qmat,   // [B*NQ, S]
    float* __restrict__ attn,         // [B*NKV, HQ]
    float* __restrict__ dpart,        // [B, NCH, HQ]
    float* __restrict__ vis)          // [B*NKV, NQ] or null
{
  extern __shared__ float sm[];
  float* Qs  = sm + QS_OFF;    // [h][q*33+d]  (h*NQ+q)*33+d
  float* lg  = sm + LG_OFF;    // [key][j] pitch 129
  float* dws = sm + DWS_OFF;   // [warp][HQ]
  const int b = blockIdx.x, ch = blockIdx.y;
  const int t = threadIdx.x;
  const int key0 = ch * KT;

  // stage Q: [16][256] -> Qs[(h*16+q)*33+d]
  const float* qb = Qmat + (size_t)b * NQ * Sd;
  for (int i = t; i < NQ * Sd; i += 256) {
    int q = i >> 8, dcol = i & 255;
    Qs[((dcol >> 5) * NQ + q) * 33 + (dcol & 31)] = qb[i];
  }
  __syncthreads();

  // compute logits: thread owns (key = t&127, head-group = t>>7)
  {
    const int key = t & 127;
    const int hbase = (t >> 7) * 4;
    const float* krow = Kmat + ((size_t)b * NKV + key0 + key) * Sd;
    #pragma unroll
    for (int hh = 0; hh < 4; hh++) {
      const int h = hbase + hh;
      float kreg[32];
      #pragma unroll
      for (int i = 0; i < 8; i++) {
        float4 k4 = *(const float4*)(krow + h * 32 + i * 4);
        kreg[i*4] = k4.x; kreg[i*4+1] = k4.y; kreg[i*4+2] = k4.z; kreg[i*4+3] = k4.w;
      }
      #pragma unroll 4
      for (int q = 0; q < NQ; q++) {
        const float* qp = Qs + (h * NQ + q) * 33;
        float acc = 0.f;
        #pragma unroll
        for (int d = 0; d < 32; d++) acc += kreg[d] * qp[d];
        lg[key * 129 + h * NQ + q] = acc;
      }
    }
  }
  __syncthreads();

  // warp-per-key softmax; j = l + 32r mapping
  const int w = t >> 5, l = t & 31;
  float dsum[4] = {0.f, 0.f, 0.f, 0.f};
  for (int i = 0; i < KT / 8; i++) {
    const int key = w + i * 8;
    float v[4];
    #pragma unroll
    for (int r = 0; r < 4; r++) v[r] = lg[key * 129 + l + 32 * r];
    float m = fmaxf(fmaxf(v[0], v[1]), fmaxf(v[2], v[3]));
    #pragma unroll
    for (int o = 16; o; o >>= 1) m = fmaxf(m, __shfl_xor_sync(0xffffffffu, m, o));
    float e[4], s = 0.f;
    #pragma unroll
    for (int r = 0; r < 4; r++) { e[r] = __expf(v[r] - m); s += e[r]; }
    #pragma unroll
    for (int o = 16; o; o >>= 1) s += __shfl_xor_sync(0xffffffffu, s, o);
    const float inv = 1.0f / s;
    float* arow = attn + ((size_t)b * NKV + key0 + key) * HQ;
    float a[4];
    #pragma unroll
    for (int r = 0; r < 4; r++) {
      a[r] = e[r] * inv;
      dsum[r] += a[r];
      arow[l + 32 * r] = a[r];
    }
    if (vis) {
      float vsum = a[0] + a[1] + a[2] + a[3];
      vsum += __shfl_xor_sync(0xffffffffu, vsum, 16);
      if (l < NQ) vis[((size_t)b * NKV + key0 + key) * NQ + l] = vsum;
    }
  }
  #pragma unroll
  for (int r = 0; r < 4; r++) dws[w * HQ + l + 32 * r] = dsum[r];
  __syncthreads();
  if (t < HQ) {
    float s = 0.f;
    #pragma unroll
    for (int ww = 0; ww < 8; ww++) s += dws[ww * HQ + t];
    dpart[((size_t)b * NCH + ch) * HQ + t] = s;
  }
}

// denom[b,j] = sum over chunks (32 reads only)
__global__ void denom_reduce2(const float* __restrict__ dpart, float* __restrict__ denom)
{
  const int b = blockIdx.x, j = threadIdx.x;
  float s = 0.f;
  #pragma unroll
  for (int c = 0; c < NCH; c++) s += dpart[((size_t)b * NCH + c) * HQ + j];
  denom[b * HQ + j] = s;
}

// ---------------- updates, key-split: grid (B, H, USPL), 256 threads ----------------
__global__ void __launch_bounds__(256) updates_split(
    const float* __restrict__ attn, const float* __restrict__ denom,
    const float* __restrict__ V, float* __restrict__ updp)
{
  __shared__ float As[UKC][NQ];
  __shared__ float Vs[UKC][HD];
  __shared__ float invd[NQ];
  const int b = blockIdx.x, h = blockIdx.y, z = blockIdx.z;
  const int tid = threadIdx.x;
  const int q0 = tid >> 5;       // 0..7
  const int d  = tid & 31;
  if (tid < NQ) invd[tid] = 1.0f / (denom[b * HQ + h * NQ + tid] + EPSn);
  __syncthreads();
  float acc[2] = {0.f, 0.f};
  const int kbeg = z * (NKV / USPL), kend = kbeg + NKV / USPL;
  for (int k0 = kbeg; k0 < kend; k0 += UKC) {
    {
      int key = tid >> 2, part = (tid & 3) * 4;
      float4 a4 = *(const float4*)(attn + ((size_t)b * NKV + k0 + key) * HQ + h * NQ + part);
      As[key][part+0] = a4.x * invd[part+0];
      As[key][part+1] = a4.y * invd[part+1];
      As[key][part+2] = a4.z * invd[part+2];
      As[key][part+3] = a4.w * invd[part+3];
    }
    #pragma unroll
    for (int r = 0; r < 2; r++) {
      int idx = tid + r * 256;
      int key = idx >> 3, part = (idx & 7) * 4;
      float4 v4 = *(const float4*)(V + ((size_t)b * NKV + k0 + key) * Sd + h * HD + part);
      *(float4*)(&Vs[key][part]) = v4;
    }
    __syncthreads();
    #pragma unroll 8
    for (int kk = 0; kk < UKC; kk++) {
      const float vv = Vs[kk][d];
      acc[0] += As[kk][q0 * 2 + 0] * vv;
      acc[1] += As[kk][q0 * 2 + 1] * vv;
    }
    __syncthreads();
  }
  #pragma unroll
  for (int i = 0; i < 2; i++) {
    const int qi = q0 * 2 + i;
    updp[((size_t)(z * Bn + b) * NQ + qi) * Sd + h * HD + d] = acc[i];
  }
}

__global__ void upd_reduce(const float* __restrict__ updp, float* __restrict__ upd)
{
  const int idx = blockIdx.x * blockDim.x + threadIdx.x;
  if (idx >= Bn * NQ * Sd) return;
  float s = 0.f;
  #pragma unroll
  for (int z = 0; z < USPL; z++) s += updp[(size_t)z * Bn * NQ * Sd + idx];
  upd[idx] = s;
}

// ---------------- GRU pointwise (gates r,z,n) ----------------
__global__ void gru_kernel(const float* __restrict__ gi, const float* __restrict__ gh,
                           const float* __restrict__ hprev, float* __restrict__ out)
{
  const int idx = blockIdx.x * blockDim.x + threadIdx.x;
  if (idx >= Bn * NQ * Sd) return;
  const int row = idx >> 8, col = idx & (Sd - 1);
  const float* gir = gi + (size_t)row * 3 * Sd;
  const float* ghr = gh + (size_t)row * 3 * Sd;
  const float ir = gir[col], iz = gir[Sd + col], in_ = gir[2 * Sd + col];
  const float hr = ghr[col], hz = ghr[Sd + col], hn = ghr[2 * Sd + col];
  const float r = 1.0f / (1.0f + __expf(-(ir + hr)));
  const float z = 1.0f / (1.0f + __expf(-(iz + hz)));
  const float n = tanhf(in_ + r * hn);
  out[idx] = (1.0f - z) * n + z * hprev[idx];
}

__global__ void bcast_slots(const float* __restrict__ s0, float* __restrict__ slots)
{
  const int idx = blockIdx.x * blockDim.x + threadIdx.x;
  if (idx < Bn * NQ * Sd) slots[idx] = s0[idx & (NQ * Sd - 1)];
}

__global__ void copy_kernel(const float* __restrict__ src, float* __restrict__ dst, int n)
{
  const int idx = blockIdx.x * blockDim.x + threadIdx.x;
  if (idx < n) dst[idx] = src[idx];
}

// ---------------- launch ----------------
extern "C" void kernel_launch(void* const* d_in, const int* in_sizes, int n_in,
                              void* d_out, int out_size)
{
  const float* slots0 = (const float*)d_in[0];
  const float* inputs = (const float*)d_in[1];
  const float* nin_g  = (const float*)d_in[2];
  const float* nin_b  = (const float*)d_in[3];
  const float* ns_g   = (const float*)d_in[4];
  const float* ns_b   = (const float*)d_in[5];
  const float* nm_g   = (const float*)d_in[6];
  const float* nm_b   = (const float*)d_in[7];
  const float* Wq     = (const float*)d_in[8];
  const float* Wk     = (const float*)d_in[9];
  const float* Wv     = (const float*)d_in[10];
  const float* wih    = (const float*)d_in[11];
  const float* whh    = (const float*)d_in[12];
  const float* bih    = (const float*)d_in[13];
  const float* bhh    = (const float*)d_in[14];
  const float* w1     = (const float*)d_in[15];
  const float* b1     = (const float*)d_in[16];
  const float* w2     = (const float*)d_in[17];
  const float* b2     = (const float*)d_in[18];
  float* out = (float*)d_out;

  float *px, *pk, *pv, *pattn, *pq, *ps, *pslots, *ptmp, *pm, *pupd, *pupdp,
        *ph1, *pgi, *pgh, *pdpart, *pdenom;
  cudaGetSymbolAddress((void**)&px, g_x);
  cudaGetSymbolAddress((void**)&pk, g_k);
  cudaGetSymbolAddress((void**)&pv, g_v);
  cudaGetSymbolAddress((void**)&pattn, g_attn);
  cudaGetSymbolAddress((void**)&pq, g_q);
  cudaGetSymbolAddress((void**)&ps, g_s);
  cudaGetSymbolAddress((void**)&pslots, g_slots);
  cudaGetSymbolAddress((void**)&ptmp, g_tmp);
  cudaGetSymbolAddress((void**)&pm, g_m);
  cudaGetSymbolAddress((void**)&pupd, g_upd);
  cudaGetSymbolAddress((void**)&pupdp, g_updp);
  cudaGetSymbolAddress((void**)&ph1, g_h1);
  cudaGetSymbolAddress((void**)&pgi, g_gi);
  cudaGetSymbolAddress((void**)&pgh, g_gh);
  cudaGetSymbolAddress((void**)&pdpart, g_dpart);
  cudaGetSymbolAddress((void**)&pdenom, g_denom);

  static bool attr_set = false;
  if (!attr_set) {
    cudaFuncSetAttribute(attn_fused, cudaFuncAttributeMaxDynamicSharedMemorySize, ATTN_SMEM_BYTES);
    attr_set = true;
  }

  const int MROWS = Bn * NKV;     // 131072
  const int SR    = Bn * NQ;      // 512
  const long long SLOTS_N = (long long)Bn * NQ * Sd;      // 131072
  const long long VIS_N   = (long long)Bn * NKV * NQ;     // 2097152

  float* slots_out = out;
  float* vis_out = ((long long)out_size >= SLOTS_N + VIS_N) ? (out + SLOTS_N) : nullptr;

  bcast_slots<<<(unsigned)((SLOTS_N + 255) / 256), 256>>>(slots0, pslots);
  ln_kernel<DIN><<<MROWS, 256>>>(inputs, nin_g, nin_b, px);
  gemm_nt<128,128,8,8,8><<<dim3(Sd/128, MROWS/128), 256>>>(px, Wk, pk, MROWS, Sd, DIN, KSCALE, nullptr, nullptr, 0);
  gemm_nt<128,128,8,8,8><<<dim3(Sd/128, MROWS/128), 256>>>(px, Wv, pv, MROWS, Sd, DIN, 1.0f,   nullptr, nullptr, 0);

  for (int it = 0; it < 3; it++) {
    ln_kernel<Sd><<<SR, 256>>>(pslots, ns_g, ns_b, ps);
    gemm_nt<64,64,8,4,4><<<dim3(Sd/64, SR/64), 256>>>(ps, Wq, pq, SR, Sd, Sd, 1.f, nullptr, nullptr, 0);
    attn_fused<<<dim3(Bn, NCH), 256, ATTN_SMEM_BYTES>>>(pk, pq, pattn, pdpart,
                                                        (it == 2) ? vis_out : nullptr);
    denom_reduce2<<<Bn, HQ>>>(pdpart, pdenom);
    updates_split<<<dim3(Bn, Hn, USPL), 256>>>(pattn, pdenom, pv, pupdp);
    upd_reduce<<<(unsigned)((SLOTS_N + 255) / 256), 256>>>(pupdp, pupd);
    gemm_nt<64,64,8,4,4><<<dim3(3*Sd/64, SR/64), 256>>>(pupd,   wih, pgi, SR, 3*Sd, Sd, 1.f, bih, nullptr, 0);
    gemm_nt<64,64,8,4,4><<<dim3(3*Sd/64, SR/64), 256>>>(pslots, whh, pgh, SR, 3*Sd, Sd, 1.f, bhh, nullptr, 0);
    gru_kernel<<<(unsigned)((SLOTS_N + 255) / 256), 256>>>(pgi, pgh, pslots, ptmp);
    ln_kernel<Sd><<<SR, 256>>>(ptmp, nm_g, nm_b, pm);
    gemm_nt<64,64,8,4,4><<<dim3(HM/64, SR/64), 256>>>(pm,  w1, ph1,    SR, HM, Sd, 1.f, b1, nullptr, 1);
    gemm_nt<64,64,8,4,4><<<dim3(Sd/64, SR/64), 256>>>(ph1, w2, pslots, SR, Sd, HM, 1.f, b2, ptmp,  0);
  }
  copy_kernel<<<(unsigned)((SLOTS_N + 255) / 256), 256>>>(pslots, slots_out, (int)SLOTS_N);
}

// round 13
// speedup vs baseline: 1.8483x; 1.3254x over previous
#include <cuda_runtime.h>
#include <cuda_bf16.h>
#include <mma.h>
#include <math.h>

using namespace nvcuda;

#define Bn   32
#define NKV  4096
#define DIN  256
#define NQ   16
#define Sd   256
#define Hn   8
#define HD   32
#define HM   512
#define HQ   128          // Hn*NQ
#define EPSn 1e-8f
#define UKC  64
#define USPL 8            // updates key-split
#define KT   128          // keys per attention block
#define NCH  (NKV/KT)     // 32
#define KSCALE 0.17677669529663687f   // 1/sqrt(32)
#define MROWSC (Bn*NKV)   // 131072

// attn_fused smem layout (floats)
#define QS_OFF  0
#define QS_SZ   (Hn*NQ*33)          // 4224
#define LG_OFF  (QS_OFF + QS_SZ)
#define LG_SZ   (KT*129)            // 16512
#define DWS_OFF (LG_OFF + LG_SZ)
#define DWS_SZ  (8*HQ)              // 1024
#define ATTN_SMEM_BYTES ((DWS_OFF + DWS_SZ) * 4)

// ---------------- scratch (static device globals; no allocations) ----------------
__device__ __nv_bfloat16 g_xhi[(size_t)MROWSC*DIN];
__device__ __nv_bfloat16 g_xlo[(size_t)MROWSC*DIN];
__device__ __nv_bfloat16 g_whi[2*Sd*DIN];      // [512,256] = Wk*kscale ; Wv
__device__ __nv_bfloat16 g_wlo[2*Sd*DIN];
__device__ float g_k[MROWSC*Sd];
__device__ float g_v[MROWSC*Sd];
__device__ float g_attn[(size_t)Bn*NKV*HQ];
__device__ float g_q[Bn*NQ*Sd];
__device__ float g_s[Bn*NQ*Sd];
__device__ float g_slots[Bn*NQ*Sd];
__device__ float g_tmp[Bn*NQ*Sd];
__device__ float g_m[Bn*NQ*Sd];
__device__ float g_upd[Bn*NQ*Sd];
__device__ float g_updp[USPL*Bn*NQ*Sd];
__device__ float g_h1[Bn*NQ*HM];
__device__ float g_gi[Bn*NQ*3*Sd];
__device__ float g_gh[Bn*NQ*3*Sd];
__device__ float g_dpart[Bn*NCH*HQ];
__device__ float g_denom[Bn*HQ];

// ---------------- LayerNorm (fp32 out) ----------------
template<int COLS>
__global__ void __launch_bounds__(256) ln_kernel(const float* __restrict__ in,
    const float* __restrict__ gamma, const float* __restrict__ beta,
    float* __restrict__ out)
{
  __shared__ float sa[8], sb[8];
  const int row = blockIdx.x;
  const float* x = in + (size_t)row * COLS;
  float* y = out + (size_t)row * COLS;
  const int tid = threadIdx.x;
  float s = 0.f, s2 = 0.f;
  for (int c = tid; c < COLS; c += 256) { float v = x[c]; s += v; s2 += v*v; }
  const int lane = tid & 31, w = tid >> 5;
  #pragma unroll
  for (int o = 16; o; o >>= 1) {
    s  += __shfl_xor_sync(0xffffffffu, s,  o);
    s2 += __shfl_xor_sync(0xffffffffu, s2, o);
  }
  if (!lane) { sa[w] = s; sb[w] = s2; }
  __syncthreads();
  float ts = 0.f, ts2 = 0.f;
  #pragma unroll
  for (int i = 0; i < 8; i++) { ts += sa[i]; ts2 += sb[i]; }
  const float mean = ts * (1.0f / COLS);
  const float var  = ts2 * (1.0f / COLS) - mean * mean;
  const float rstd = rsqrtf(var + 1e-5f);
  for (int c = tid; c < COLS; c += 256)
    y[c] = (x[c] - mean) * rstd * gamma[c] + beta[c];
}

// ---------------- LayerNorm with bf16 hi/lo split output ----------------
__global__ void __launch_bounds__(256) ln_split_kernel(const float* __restrict__ in,
    const float* __restrict__ gamma, const float* __restrict__ beta,
    __nv_bfloat16* __restrict__ yhi, __nv_bfloat16* __restrict__ ylo)
{
  __shared__ float sa[8], sb[8];
  const int row = blockIdx.x;
  const float* x = in + (size_t)row * DIN;
  const int tid = threadIdx.x;
  float v0 = x[tid];
  float s = v0, s2 = v0 * v0;
  const int lane = tid & 31, w = tid >> 5;
  #pragma unroll
  for (int o = 16; o; o >>= 1) {
    s  += __shfl_xor_sync(0xffffffffu, s,  o);
    s2 += __shfl_xor_sync(0xffffffffu, s2, o);
  }
  if (!lane) { sa[w] = s; sb[w] = s2; }
  __syncthreads();
  float ts = 0.f, ts2 = 0.f;
  #pragma unroll
  for (int i = 0; i < 8; i++) { ts += sa[i]; ts2 += sb[i]; }
  const float mean = ts * (1.0f / DIN);
  const float var  = ts2 * (1.0f / DIN) - mean * mean;
  const float rstd = rsqrtf(var + 1e-5f);
  const float y = (v0 - mean) * rstd * gamma[tid] + beta[tid];
  const __nv_bfloat16 hi = __float2bfloat16(y);
  const __nv_bfloat16 lo = __float2bfloat16(y - __bfloat162float(hi));
  yhi[(size_t)row * DIN + tid] = hi;
  ylo[(size_t)row * DIN + tid] = lo;
}

// ---------------- weight split: [Wk*kscale ; Wv] -> bf16 hi/lo ----------------
__global__ void w_split_kernel(const float* __restrict__ Wk, const float* __restrict__ Wv,
                               __nv_bfloat16* __restrict__ whi, __nv_bfloat16* __restrict__ wlo)
{
  const int i = blockIdx.x * blockDim.x + threadIdx.x;
  if (i >= 2 * Sd * DIN) return;
  float w = (i < Sd * DIN) ? Wk[i] * KSCALE : Wv[i - Sd * DIN];
  const __nv_bfloat16 hi = __float2bfloat16(w);
  const __nv_bfloat16 lo = __float2bfloat16(w - __bfloat162float(hi));
  whi[i] = hi; wlo[i] = lo;
}

// ---------------- bf16-split tensor-core GEMM for K/V projections ----------------
// C[M, 512] = Xsplit[M,256] @ Wsplit[512,256]^T ; cols 0-255 -> Kout, 256-511 -> Vout
// BM=128, BN=128, BK=32; 256 threads (8 warps, 4x2), warp tile 32x64.
__global__ void __launch_bounds__(256) gemm_bf16split(
    const __nv_bfloat16* __restrict__ Ahi, const __nv_bfloat16* __restrict__ Alo,
    const __nv_bfloat16* __restrict__ Bhi, const __nv_bfloat16* __restrict__ Blo,
    float* __restrict__ Kout, float* __restrict__ Vout)
{
  __shared__ __nv_bfloat16 Ah[128][40], Al[128][40], Bh[128][40], Bl[128][40];
  const int t = threadIdx.x;
  const int wid = t >> 5;
  const int warp_m = wid & 3;          // 0..3 -> 32-row slice
  const int warp_n = wid >> 2;         // 0..1 -> 64-col slice
  const int bn = blockIdx.x * 128;
  const int bm = blockIdx.y * 128;

  wmma::fragment<wmma::accumulator, 16, 16, 16, float> c[2][4];
  #pragma unroll
  for (int i = 0; i < 2; i++)
    #pragma unroll
    for (int j = 0; j < 4; j++) wmma::fill_fragment(c[i][j], 0.0f);

  for (int k0 = 0; k0 < DIN; k0 += 32) {
    // load A tiles (128x32) hi+lo and B tiles (128x32) hi+lo, 16B chunks
    #pragma unroll
    for (int r = 0; r < 2; r++) {
      const int i = t + r * 256;            // 0..511
      const int row = i >> 2, seg = (i & 3) * 8;
      *(uint4*)&Ah[row][seg] = *(const uint4*)(Ahi + (size_t)(bm + row) * DIN + k0 + seg);
      *(uint4*)&Al[row][seg] = *(const uint4*)(Alo + (size_t)(bm + row) * DIN + k0 + seg);
      *(uint4*)&Bh[row][seg] = *(const uint4*)(Bhi + (size_t)(bn + row) * DIN + k0 + seg);
      *(uint4*)&Bl[row][seg] = *(const uint4*)(Blo + (size_t)(bn + row) * DIN + k0 + seg);
    }
    __syncthreads();
    #pragma unroll
    for (int kk = 0; kk < 2; kk++) {
      wmma::fragment<wmma::matrix_a, 16, 16, 16, __nv_bfloat16, wmma::row_major> ah[2], al[2];
      wmma::fragment<wmma::matrix_b, 16, 16, 16, __nv_bfloat16, wmma::col_major> bh[4], bl[4];
      #pragma unroll
      for (int i = 0; i < 2; i++) {
        wmma::load_matrix_sync(ah[i], &Ah[warp_m * 32 + i * 16][kk * 16], 40);
        wmma::load_matrix_sync(al[i], &Al[warp_m * 32 + i * 16][kk * 16], 40);
      }
      #pragma unroll
      for (int j = 0; j < 4; j++) {
        wmma::load_matrix_sync(bh[j], &Bh[warp_n * 64 + j * 16][kk * 16], 40);
        wmma::load_matrix_sync(bl[j], &Bl[warp_n * 64 + j * 16][kk * 16], 40);
      }
      #pragma unroll
      for (int i = 0; i < 2; i++)
        #pragma unroll
        for (int j = 0; j < 4; j++) {
          wmma::mma_sync(c[i][j], ah[i], bh[j], c[i][j]);
          wmma::mma_sync(c[i][j], ah[i], bl[j], c[i][j]);
          wmma::mma_sync(c[i][j], al[i], bh[j], c[i][j]);
        }
    }
    __syncthreads();
  }

  // epilogue: whole block lands in one half (bn in {0,128} -> K, {256,384} -> V)
  float* dstBase = (bn < Sd) ? (Kout + bn) : (Vout + (bn - Sd));
  #pragma unroll
  for (int i = 0; i < 2; i++) {
    const int mrow = bm + warp_m * 32 + i * 16;
    #pragma unroll
    for (int j = 0; j < 4; j++) {
      const int ncol = warp_n * 64 + j * 16;
      wmma::store_matrix_sync(dstBase + (size_t)mrow * Sd + ncol, c[i][j], Sd, wmma::mem_row_major);
    }
  }
}

// ---------------- GEMM: C[M,N] = alpha * A[M,K] @ B[N,K]^T (+bias)(+residual)(relu) ----------------
template<int BM, int BN, int BK, int TM, int TN>
__global__ void __launch_bounds__(256) gemm_nt(
    const float* __restrict__ A, const float* __restrict__ Bm, float* __restrict__ C,
    int M, int N, int K, float alpha, const float* __restrict__ bias,
    const float* __restrict__ residual, int relu)
{
  __shared__ float As[BK][BM];
  __shared__ float Bs[BK][BN];
  const int tid = threadIdx.x;
  const int bn = blockIdx.x * BN, bm = blockIdx.y * BM;
  const int TXN = BN / TN;
  const int tx = tid % TXN, ty = tid / TXN;
  float acc[TM][TN];
  #pragma unroll
  for (int i = 0; i < TM; i++)
    #pragma unroll
    for (int j = 0; j < TN; j++) acc[i][j] = 0.f;

  for (int k0 = 0; k0 < K; k0 += BK) {
    for (int i = tid * 4; i < BM * BK; i += 1024) {
      int r = i / BK, c = i % BK;
      float4 a4 = *(const float4*)(A + (size_t)(bm + r) * K + k0 + c);
      As[c][r] = a4.x; As[c+1][r] = a4.y; As[c+2][r] = a4.z; As[c+3][r] = a4.w;
    }
    for (int i = tid * 4; i < BN * BK; i += 1024) {
      int r = i / BK, c = i % BK;
      float4 b4 = *(const float4*)(Bm + (size_t)(bn + r) * K + k0 + c);
      Bs[c][r] = b4.x; Bs[c+1][r] = b4.y; Bs[c+2][r] = b4.z; Bs[c+3][r] = b4.w;
    }
    __syncthreads();
    #pragma unroll
    for (int kk = 0; kk < BK; kk++) {
      float a[TM], bfr[TN];
      #pragma unroll
      for (int i = 0; i < TM; i++) a[i] = As[kk][ty * TM + i];
      #pragma unroll
      for (int j = 0; j < TN; j++) bfr[j] = Bs[kk][tx * TN + j];
      #pragma unroll
      for (int i = 0; i < TM; i++)
        #pragma unroll
        for (int j = 0; j < TN; j++) acc[i][j] += a[i] * bfr[j];
    }
    __syncthreads();
  }
  #pragma unroll
  for (int i = 0; i < TM; i++) {
    const int m = bm + ty * TM + i;
    #pragma unroll
    for (int j = 0; j < TN; j++) {
      const int n = bn + tx * TN + j;
      float v = acc[i][j] * alpha;
      if (bias)     v += bias[n];
      if (residual) v += residual[(size_t)m * N + n];
      if (relu)     v = fmaxf(v, 0.f);
      C[(size_t)m * N + n] = v;
    }
  }
}

// ---------------- fused attention: logits + softmax + denom partials + vis ----------------
__global__ void __launch_bounds__(256) attn_fused(
    const float* __restrict__ Kmat, const float* __restrict__ Qmat,
    float* __restrict__ attn, float* __restrict__ dpart, float* __restrict__ vis)
{
  extern __shared__ float sm[];
  float* Qs  = sm + QS_OFF;
  float* lg  = sm + LG_OFF;
  float* dws = sm + DWS_OFF;
  const int b = blockIdx.x, ch = blockIdx.y;
  const int t = threadIdx.x;
  const int key0 = ch * KT;

  const float* qb = Qmat + (size_t)b * NQ * Sd;
  for (int i = t; i < NQ * Sd; i += 256) {
    int q = i >> 8, dcol = i & 255;
    Qs[((dcol >> 5) * NQ + q) * 33 + (dcol & 31)] = qb[i];
  }
  __syncthreads();

  {
    const int key = t & 127;
    const int hbase = (t >> 7) * 4;
    const float* krow = Kmat + ((size_t)b * NKV + key0 + key) * Sd;
    #pragma unroll
    for (int hh = 0; hh < 4; hh++) {
      const int h = hbase + hh;
      float kreg[32];
      #pragma unroll
      for (int i = 0; i < 8; i++) {
        float4 k4 = *(const float4*)(krow + h * 32 + i * 4);
        kreg[i*4] = k4.x; kreg[i*4+1] = k4.y; kreg[i*4+2] = k4.z; kreg[i*4+3] = k4.w;
      }
      #pragma unroll 4
      for (int q = 0; q < NQ; q++) {
        const float* qp = Qs + (h * NQ + q) * 33;
        float acc = 0.f;
        #pragma unroll
        for (int d = 0; d < 32; d++) acc += kreg[d] * qp[d];
        lg[key * 129 + h * NQ + q] = acc;
      }
    }
  }
  __syncthreads();

  const int w = t >> 5, l = t & 31;
  float dsum[4] = {0.f, 0.f, 0.f, 0.f};
  for (int i = 0; i < KT / 8; i++) {
    const int key = w + i * 8;
    float v[4];
    #pragma unroll
    for (int r = 0; r < 4; r++) v[r] = lg[key * 129 + l + 32 * r];
    float m = fmaxf(fmaxf(v[0], v[1]), fmaxf(v[2], v[3]));
    #pragma unroll
    for (int o = 16; o; o >>= 1) m = fmaxf(m, __shfl_xor_sync(0xffffffffu, m, o));
    float e[4], s = 0.f;
    #pragma unroll
    for (int r = 0; r < 4; r++) { e[r] = __expf(v[r] - m); s += e[r]; }
    #pragma unroll
    for (int o = 16; o; o >>= 1) s += __shfl_xor_sync(0xffffffffu, s, o);
    const float inv = 1.0f / s;
    float* arow = attn + ((size_t)b * NKV + key0 + key) * HQ;
    float a[4];
    #pragma unroll
    for (int r = 0; r < 4; r++) {
      a[r] = e[r] * inv;
      dsum[r] += a[r];
      arow[l + 32 * r] = a[r];
    }
    if (vis) {
      float vsum = a[0] + a[1] + a[2] + a[3];
      vsum += __shfl_xor_sync(0xffffffffu, vsum, 16);
      if (l < NQ) vis[((size_t)b * NKV + key0 + key) * NQ + l] = vsum;
    }
  }
  #pragma unroll
  for (int r = 0; r < 4; r++) dws[w * HQ + l + 32 * r] = dsum[r];
  __syncthreads();
  if (t < HQ) {
    float s = 0.f;
    #pragma unroll
    for (int ww = 0; ww < 8; ww++) s += dws[ww * HQ + t];
    dpart[((size_t)b * NCH + ch) * HQ + t] = s;
  }
}

__global__ void denom_reduce2(const float* __restrict__ dpart, float* __restrict__ denom)
{
  const int b = blockIdx.x, j = threadIdx.x;
  float s = 0.f;
  #pragma unroll
  for (int c = 0; c < NCH; c++) s += dpart[((size_t)b * NCH + c) * HQ + j];
  denom[b * HQ + j] = s;
}

// ---------------- updates, key-split ----------------
__global__ void __launch_bounds__(256) updates_split(
    const float* __restrict__ attn, const float* __restrict__ denom,
    const float* __restrict__ V, float* __restrict__ updp)
{
  __shared__ float As[UKC][NQ];
  __shared__ float Vs[UKC][HD];
  __shared__ float invd[NQ];
  const int b = blockIdx.x, h = blockIdx.y, z = blockIdx.z;
  const int tid = threadIdx.x;
  const int q0 = tid >> 5;
  const int d  = tid & 31;
  if (tid < NQ) invd[tid] = 1.0f / (denom[b * HQ + h * NQ + tid] + EPSn);
  __syncthreads();
  float acc[2] = {0.f, 0.f};
  const int kbeg = z * (NKV / USPL), kend = kbeg + NKV / USPL;
  for (int k0 = kbeg; k0 < kend; k0 += UKC) {
    {
      int key = tid >> 2, part = (tid & 3) * 4;
      float4 a4 = *(const float4*)(attn + ((size_t)b * NKV + k0 + key) * HQ + h * NQ + part);
      As[key][part+0] = a4.x * invd[part+0];
      As[key][part+1] = a4.y * invd[part+1];
      As[key][part+2] = a4.z * invd[part+2];
      As[key][part+3] = a4.w * invd[part+3];
    }
    #pragma unroll
    for (int r = 0; r < 2; r++) {
      int idx = tid + r * 256;
      int key = idx >> 3, part = (idx & 7) * 4;
      float4 v4 = *(const float4*)(V + ((size_t)b * NKV + k0 + key) * Sd + h * HD + part);
      *(float4*)(&Vs[key][part]) = v4;
    }
    __syncthreads();
    #pragma unroll 8
    for (int kk = 0; kk < UKC; kk++) {
      const float vv = Vs[kk][d];
      acc[0] += As[kk][q0 * 2 + 0] * vv;
      acc[1] += As[kk][q0 * 2 + 1] * vv;
    }
    __syncthreads();
  }
  #pragma unroll
  for (int i = 0; i < 2; i++) {
    const int qi = q0 * 2 + i;
    updp[((size_t)(z * Bn + b) * NQ + qi) * Sd + h * HD + d] = acc[i];
  }
}

__global__ void upd_reduce(const float* __restrict__ updp, float* __restrict__ upd)
{
  const int idx = blockIdx.x * blockDim.x + threadIdx.x;
  if (idx >= Bn * NQ * Sd) return;
  float s = 0.f;
  #pragma unroll
  for (int z = 0; z < USPL; z++) s += updp[(size_t)z * Bn * NQ * Sd + idx];
  upd[idx] = s;
}

// ---------------- GRU pointwise ----------------
__global__ void gru_kernel(const float* __restrict__ gi, const float* __restrict__ gh,
                           const float* __restrict__ hprev, float* __restrict__ out)
{
  const int idx = blockIdx.x * blockDim.x + threadIdx.x;
  if (idx >= Bn * NQ * Sd) return;
  const int row = idx >> 8, col = idx & (Sd - 1);
  const float* gir = gi + (size_t)row * 3 * Sd;
  const float* ghr = gh + (size_t)row * 3 * Sd;
  const float ir = gir[col], iz = gir[Sd + col], in_ = gir[2 * Sd + col];
  const float hr = ghr[col], hz = ghr[Sd + col], hn = ghr[2 * Sd + col];
  const float r = 1.0f / (1.0f + __expf(-(ir + hr)));
  const float z = 1.0f / (1.0f + __expf(-(iz + hz)));
  const float n = tanhf(in_ + r * hn);
  out[idx] = (1.0f - z) * n + z * hprev[idx];
}

__global__ void bcast_slots(const float* __restrict__ s0, float* __restrict__ slots)
{
  const int idx = blockIdx.x * blockDim.x + threadIdx.x;
  if (idx < Bn * NQ * Sd) slots[idx] = s0[idx & (NQ * Sd - 1)];
}

__global__ void copy_kernel(const float* __restrict__ src, float* __restrict__ dst, int n)
{
  const int idx = blockIdx.x * blockDim.x + threadIdx.x;
  if (idx < n) dst[idx] = src[idx];
}

// ---------------- launch ----------------
extern "C" void kernel_launch(void* const* d_in, const int* in_sizes, int n_in,
                              void* d_out, int out_size)
{
  const float* slots0 = (const float*)d_in[0];
  const float* inputs = (const float*)d_in[1];
  const float* nin_g  = (const float*)d_in[2];
  const float* nin_b  = (const float*)d_in[3];
  const float* ns_g   = (const float*)d_in[4];
  const float* ns_b   = (const float*)d_in[5];
  const float* nm_g   = (const float*)d_in[6];
  const float* nm_b   = (const float*)d_in[7];
  const float* Wq     = (const float*)d_in[8];
  const float* Wk     = (const float*)d_in[9];
  const float* Wv     = (const float*)d_in[10];
  const float* wih    = (const float*)d_in[11];
  const float* whh    = (const float*)d_in[12];
  const float* bih    = (const float*)d_in[13];
  const float* bhh    = (const float*)d_in[14];
  const float* w1     = (const float*)d_in[15];
  const float* b1     = (const float*)d_in[16];
  const float* w2     = (const float*)d_in[17];
  const float* b2     = (const float*)d_in[18];
  float* out = (float*)d_out;

  __nv_bfloat16 *pxhi, *pxlo, *pwhi, *pwlo;
  float *pk, *pv, *pattn, *pq, *ps, *pslots, *ptmp, *pm, *pupd, *pupdp,
        *ph1, *pgi, *pgh, *pdpart, *pdenom;
  cudaGetSymbolAddress((void**)&pxhi, g_xhi);
  cudaGetSymbolAddress((void**)&pxlo, g_xlo);
  cudaGetSymbolAddress((void**)&pwhi, g_whi);
  cudaGetSymbolAddress((void**)&pwlo, g_wlo);
  cudaGetSymbolAddress((void**)&pk, g_k);
  cudaGetSymbolAddress((void**)&pv, g_v);
  cudaGetSymbolAddress((void**)&pattn, g_attn);
  cudaGetSymbolAddress((void**)&pq, g_q);
  cudaGetSymbolAddress((void**)&ps, g_s);
  cudaGetSymbolAddress((void**)&pslots, g_slots);
  cudaGetSymbolAddress((void**)&ptmp, g_tmp);
  cudaGetSymbolAddress((void**)&pm, g_m);
  cudaGetSymbolAddress((void**)&pupd, g_upd);
  cudaGetSymbolAddress((void**)&pupdp, g_updp);
  cudaGetSymbolAddress((void**)&ph1, g_h1);
  cudaGetSymbolAddress((void**)&pgi, g_gi);
  cudaGetSymbolAddress((void**)&pgh, g_gh);
  cudaGetSymbolAddress((void**)&pdpart, g_dpart);
  cudaGetSymbolAddress((void**)&pdenom, g_denom);

  static bool attr_set = false;
  if (!attr_set) {
    cudaFuncSetAttribute(attn_fused, cudaFuncAttributeMaxDynamicSharedMemorySize, ATTN_SMEM_BYTES);
    attr_set = true;
  }

  const int SR = Bn * NQ;       // 512
  const long long SLOTS_N = (long long)Bn * NQ * Sd;      // 131072
  const long long VIS_N   = (long long)Bn * NKV * NQ;     // 2097152

  float* slots_out = out;
  float* vis_out = ((long long)out_size >= SLOTS_N + VIS_N) ? (out + SLOTS_N) : nullptr;

  bcast_slots<<<(unsigned)((SLOTS_N + 255) / 256), 256>>>(slots0, pslots);
  ln_split_kernel<<<MROWSC, 256>>>(inputs, nin_g, nin_b, pxhi, pxlo);
  w_split_kernel<<<(2 * Sd * DIN + 255) / 256, 256>>>(Wk, Wv, pwhi, pwlo);
  gemm_bf16split<<<dim3(4, MROWSC / 128), 256>>>(pxhi, pxlo, pwhi, pwlo, pk, pv);

  for (int it = 0; it < 3; it++) {
    ln_kernel<Sd><<<SR, 256>>>(pslots, ns_g, ns_b, ps);
    gemm_nt<64,64,8,4,4><<<dim3(Sd/64, SR/64), 256>>>(ps, Wq, pq, SR, Sd, Sd, 1.f, nullptr, nullptr, 0);
    attn_fused<<<dim3(Bn, NCH), 256, ATTN_SMEM_BYTES>>>(pk, pq, pattn, pdpart,
                                                        (it == 2) ? vis_out : nullptr);
    denom_reduce2<<<Bn, HQ>>>(pdpart, pdenom);
    updates_split<<<dim3(Bn, Hn, USPL), 256>>>(pattn, pdenom, pv, pupdp);
    upd_reduce<<<(unsigned)((SLOTS_N + 255) / 256), 256>>>(pupdp, pupd);
    gemm_nt<64,64,8,4,4><<<dim3(3*Sd/64, SR/64), 256>>>(pupd,   wih, pgi, SR, 3*Sd, Sd, 1.f, bih, nullptr, 0);
    gemm_nt<64,64,8,4,4><<<dim3(3*Sd/64, SR/64), 256>>>(pslots, whh, pgh, SR, 3*Sd, Sd, 1.f, bhh, nullptr, 0);
    gru_kernel<<<(unsigned)((SLOTS_N + 255) / 256), 256>>>(pgi, pgh, pslots, ptmp);
    ln_kernel<Sd><<<SR, 256>>>(ptmp, nm_g, nm_b, pm);
    gemm_nt<64,64,8,4,4><<<dim3(HM/64, SR/64), 256>>>(pm,  w1, ph1,    SR, HM, Sd, 1.f, b1, nullptr, 1);
    gemm_nt<64,64,8,4,4><<<dim3(Sd/64, SR/64), 256>>>(ph1, w2, pslots, SR, Sd, HM, 1.f, b2, ptmp,  0);
  }
  copy_kernel<<<(unsigned)((SLOTS_N + 255) / 256), 256>>>(pslots, slots_out, (int)SLOTS_N);
}